// round 14
// baseline (speedup 1.0000x reference)
#include <cuda_runtime.h>
#include <cuda_bf16.h>
#include <math.h>
#include <stdint.h>

#define FULLMASK 0xffffffffu

// ---------------- persistent device scratch ----------------
__device__ float g_W0T[1536 * 2048];      // layer0 weights [k][j*4+gate] (k: emb|ctx|h0)
__device__ float g_W1T[1024 * 2048];      // layer1 weights [k][j*4+gate] (k: h0|h1)
__device__ float g_b0[2048];
__device__ float g_b1[2048];
__device__ float g_embT[64 * 512 * 32];   // embeddings [t][k][b]
__device__ float g_emb0[64 * 2048 * 32];  // precomputed emb @ W0e, [t][jj][b]
__device__ float g_f1[32 * 512];
__device__ float g_h0T[512 * 32];         // h0 state [j][b]
__device__ float g_h1T[512 * 32];         // h1 state [j][b]
__device__ float g_c0T[512 * 32];
__device__ float g_c1T[512 * 32];
__device__ float g_ctxT[512 * 32];
__device__ float g_part0[128 * 8192];     // [jx*16+ks][(jloc*4+g)*32+b]  (slots 8-15 = h0-half)
__device__ float g_part1[128 * 8192];     // (slots 8-15 = h1-half)
// bf16 split operands for tensor-core FC
__device__ __align__(16) __nv_bfloat16 g_hsH[2048 * 512];
__device__ __align__(16) __nv_bfloat16 g_hsL[2048 * 512];
__device__ __align__(16) __nv_bfloat16 g_fcwH[32000 * 512];
__device__ __align__(16) __nv_bfloat16 g_fcwL[32000 * 512];

// ---------------- helpers ----------------
static __device__ __forceinline__ float sigmoidf_(float x) { return 1.f / (1.f + expf(-x)); }

static __device__ __forceinline__ float warp_sum(float v) {
#pragma unroll
    for (int o = 16; o; o >>= 1) v += __shfl_xor_sync(FULLMASK, v, o);
    return v;
}

static __device__ __forceinline__ unsigned long long pack2(float lo, float hi) {
    unsigned long long r;
    asm("mov.b64 %0, {%1, %2};" : "=l"(r) : "f"(lo), "f"(hi));
    return r;
}
static __device__ __forceinline__ void unpack2(unsigned long long v, float& lo, float& hi) {
    asm("mov.b64 {%0, %1}, %2;" : "=f"(lo), "=f"(hi) : "l"(v));
}
#define FMA2(acc, a, b) asm("fma.rn.f32x2 %0, %1, %2, %0;" : "+l"(acc) : "l"(a), "l"(b))

static __device__ __forceinline__ uint32_t smem_to_u32(const void* p) {
    uint32_t a;
    asm("{ .reg .u64 tmp; cvta.to.shared.u64 tmp, %1; cvt.u32.u64 %0, tmp; }" : "=r"(a) : "l"(p));
    return a;
}

#define GDC_WAIT()    asm volatile("griddepcontrol.wait;" ::: "memory")
#define GDC_TRIGGER() asm volatile("griddepcontrol.launch_dependents;" ::: "memory")

#define LDMATRIX_X4(r0, r1, r2, r3, addr) \
    asm volatile("ldmatrix.sync.aligned.m8n8.x4.shared.b16 {%0,%1,%2,%3}, [%4];" \
                 : "=r"(r0), "=r"(r1), "=r"(r2), "=r"(r3) : "r"(addr))
#define LDMATRIX_X2(r0, r1, addr) \
    asm volatile("ldmatrix.sync.aligned.m8n8.x2.shared.b16 {%0,%1}, [%2];" \
                 : "=r"(r0), "=r"(r1) : "r"(addr))

#define MMA_BF16(c, a, b) \
    asm volatile("mma.sync.aligned.m16n8k16.row.col.f32.bf16.bf16.f32 " \
                 "{%0,%1,%2,%3}, {%4,%5,%6,%7}, {%8,%9}, {%0,%1,%2,%3};" \
                 : "+f"((c)[0]), "+f"((c)[1]), "+f"((c)[2]), "+f"((c)[3]) \
                 : "r"((a)[0]), "r"((a)[1]), "r"((a)[2]), "r"((a)[3]), \
                   "r"((b)[0]), "r"((b)[1]))

// ---------------- GEMM partial helper: 64-k-chunk, 4 gates x 8 b ----------------
static __device__ __forceinline__ void mm_chunk(const float* __restrict__ W0,
                                                const float* xs, int j, int bg,
                                                float* __restrict__ dst_slot) {
    const float4* W = (const float4*)(W0 + j * 4);
    unsigned long long acc[4][4];
#pragma unroll
    for (int g = 0; g < 4; g++)
#pragma unroll
        for (int p = 0; p < 4; p++) acc[g][p] = 0ull;
    const float* xr = xs + bg * 8;
#pragma unroll 8
    for (int k = 0; k < 64; k++) {
        float4 w = W[(size_t)k * 512];
        unsigned long long wx = pack2(w.x, w.x);
        unsigned long long wy = pack2(w.y, w.y);
        unsigned long long wz = pack2(w.z, w.z);
        unsigned long long ww = pack2(w.w, w.w);
        const unsigned long long* xp = (const unsigned long long*)(xr + k * 32);
#pragma unroll
        for (int p = 0; p < 4; p++) {
            unsigned long long xv = xp[p];
            FMA2(acc[0][p], wx, xv);
            FMA2(acc[1][p], wy, xv);
            FMA2(acc[2][p], wz, xv);
            FMA2(acc[3][p], ww, xv);
        }
    }
    float* dst = dst_slot + (j * 4) * 32 + bg * 8;
#pragma unroll
    for (int g = 0; g < 4; g++)
#pragma unroll
        for (int p = 0; p < 4; p++) {
            float lo, hi;
            unpack2(acc[g][p], lo, hi);
            *(float2*)(dst + g * 32 + 2 * p) = make_float2(lo, hi);
        }
}

// reduce the 8 h-half partial slots (slots 8..15) for output row j, batch b
static __device__ __forceinline__ void reduce_gates_half(const float* __restrict__ part,
                                                         int j, int b,
                                                         float& s0, float& s1,
                                                         float& s2, float& s3) {
    const float* base = part + ((size_t)(j >> 6) * 16 + 8) * 8192 + ((j & 63) * 4) * 32 + b;
#pragma unroll
    for (int k2 = 0; k2 < 8; k2++) {
        const float* p = base + (size_t)k2 * 8192;
        s0 += p[0];
        s1 += p[32];
        s2 += p[64];
        s3 += p[96];
    }
}

// inline dot: s[g] += sum_k W[k][j*4+g] * x[k][b]   (W row stride 2048, 512 k's)
static __device__ __forceinline__ void dot_gates(const float* __restrict__ Wbase,
                                                 const float* __restrict__ x,
                                                 int j, int b,
                                                 float& s0, float& s1,
                                                 float& s2, float& s3) {
    const float4* W = (const float4*)(Wbase + j * 4);
    const float* xp = x + b;
#pragma unroll 8
    for (int k = 0; k < 512; k++) {
        float4 w = W[(size_t)k * 512];
        float xv = xp[k * 32];
        s0 = fmaf(w.x, xv, s0);
        s1 = fmaf(w.y, xv, s1);
        s2 = fmaf(w.z, xv, s2);
        s3 = fmaf(w.w, xv, s3);
    }
}

// ---------------- weight preprocessing (tiled transpose) ----------------
__global__ __launch_bounds__(256) void prepW0_kernel(const float* __restrict__ wih0,
                                                     const float* __restrict__ whh0) {
    GDC_WAIT();
    __shared__ float tile[32][33];
    int jj0 = blockIdx.x * 32;
    int k0 = blockIdx.y * 32;
    int tx = threadIdx.x & 31, ty = threadIdx.x >> 5;
    for (int jjl = ty; jjl < 32; jjl += 8) {
        int jj = jj0 + jjl;
        int j = jj >> 2, g = jj & 3;
        int row = g * 512 + j;
        int k = k0 + tx;
        float v = (k < 1024) ? wih0[row * 1024 + k] : whh0[row * 512 + (k - 1024)];
        tile[jjl][tx] = v;
    }
    __syncthreads();
    for (int kl = ty; kl < 32; kl += 8)
        g_W0T[(size_t)(k0 + kl) * 2048 + jj0 + tx] = tile[tx][kl];
    GDC_TRIGGER();
}

__global__ __launch_bounds__(256) void prepW1_kernel(const float* __restrict__ wih1,
                                                     const float* __restrict__ whh1) {
    GDC_WAIT();
    __shared__ float tile[32][33];
    int jj0 = blockIdx.x * 32;
    int k0 = blockIdx.y * 32;
    int tx = threadIdx.x & 31, ty = threadIdx.x >> 5;
    for (int jjl = ty; jjl < 32; jjl += 8) {
        int jj = jj0 + jjl;
        int j = jj >> 2, g = jj & 3;
        int row = g * 512 + j;
        int k = k0 + tx;
        float v = (k < 512) ? wih1[row * 512 + k] : whh1[row * 512 + (k - 512)];
        tile[jjl][tx] = v;
    }
    __syncthreads();
    for (int kl = ty; kl < 32; kl += 8)
        g_W1T[(size_t)(k0 + kl) * 2048 + jj0 + tx] = tile[tx][kl];
    GDC_TRIGGER();
}

__global__ __launch_bounds__(256) void prepB_kernel(const float* __restrict__ bih0,
                                                    const float* __restrict__ bhh0,
                                                    const float* __restrict__ bih1,
                                                    const float* __restrict__ bhh1) {
    GDC_WAIT();
    int jj = blockIdx.x * 256 + threadIdx.x;
    int j = jj >> 2, g = jj & 3;
    int row = g * 512 + j;
    g_b0[jj] = bih0[row] + bhh0[row];
    g_b1[jj] = bih1[row] + bhh1[row];
    GDC_TRIGGER();
}

__global__ __launch_bounds__(256) void splitW_kernel(const float* __restrict__ fcw) {
    GDC_WAIT();
    int idx = (blockIdx.x * 256 + threadIdx.x) * 4;   // < 32000*512
    float4 v = *(const float4*)(fcw + idx);
    __nv_bfloat16 h0 = __float2bfloat16(v.x), h1 = __float2bfloat16(v.y);
    __nv_bfloat16 h2 = __float2bfloat16(v.z), h3 = __float2bfloat16(v.w);
    __nv_bfloat162 hA, hB, lA, lB;
    hA.x = h0; hA.y = h1; hB.x = h2; hB.y = h3;
    lA.x = __float2bfloat16(v.x - __bfloat162float(h0));
    lA.y = __float2bfloat16(v.y - __bfloat162float(h1));
    lB.x = __float2bfloat16(v.z - __bfloat162float(h2));
    lB.y = __float2bfloat16(v.w - __bfloat162float(h3));
    *(__nv_bfloat162*)(g_fcwH + idx) = hA;
    *(__nv_bfloat162*)(g_fcwH + idx + 2) = hB;
    *(__nv_bfloat162*)(g_fcwL + idx) = lA;
    *(__nv_bfloat162*)(g_fcwL + idx + 2) = lB;
    GDC_TRIGGER();
}

// ---------------- embedding gather: embT[t][k][b] ----------------
__global__ __launch_bounds__(256) void embed_kernel(const int* __restrict__ cap,
                                                    const float* __restrict__ table) {
    GDC_WAIT();
    int idx = blockIdx.x * 256 + threadIdx.x;
    int b = idx >> 15;
    int t = (idx >> 9) & 63;
    int k = idx & 511;
    int tok = cap[b * 64 + t];
    g_embT[(t * 512 + k) * 32 + b] = table[(size_t)tok * 512 + k];
    GDC_TRIGGER();
}

// ---------------- feature MLP ----------------
__global__ __launch_bounds__(256) void feat1_kernel(const float* __restrict__ features,
                                                    const float* __restrict__ w,
                                                    const float* __restrict__ bias) {
    GDC_WAIT();
    int gid = blockIdx.x * 8 + (threadIdx.x >> 5);
    int lane = threadIdx.x & 31;
    int b = gid >> 9, j = gid & 511;
    const float* fr = features + b * 2048;
    const float* wr = w + j * 2048;
    float a = 0.f;
    for (int k = lane; k < 2048; k += 32) a = fmaf(fr[k], wr[k], a);
    a = warp_sum(a);
    if (!lane) g_f1[gid] = fmaxf(a + bias[j], 0.f);
    GDC_TRIGGER();
}

__global__ __launch_bounds__(256) void feat2_kernel(const float* __restrict__ w,
                                                    const float* __restrict__ bias) {
    GDC_WAIT();
    int gid = blockIdx.x * 8 + (threadIdx.x >> 5);
    int lane = threadIdx.x & 31;
    int b = gid >> 9, j = gid & 511;
    const float* fr = g_f1 + b * 512;
    const float* wr = w + j * 512;
    float a = 0.f;
    for (int k = lane; k < 512; k += 32) a = fmaf(fr[k], wr[k], a);
    a = warp_sum(a);
    if (!lane) {
        float v = a + bias[j];
        int jb = j * 32 + b;
        g_h0T[jb] = v;
        g_h1T[jb] = v;
        g_c0T[jb] = v;
        g_c1T[jb] = v;
    }
    GDC_TRIGGER();
}

// ---------------- precompute emb @ W0e for all t ----------------
__global__ __launch_bounds__(256) void lstm0_pre_kernel() {
    GDC_WAIT();
    __shared__ float xs[64 * 32];
    int jx = blockIdx.x, t = blockIdx.y;
    int tid = threadIdx.x;
    int j = tid & 63, bg = tid >> 6;
    int jjbase = (jx * 64 + j) * 4;
    const float* embt = g_embT + (size_t)t * 512 * 32;

    unsigned long long acc[4][4];
#pragma unroll
    for (int g = 0; g < 4; g++)
#pragma unroll
        for (int p = 0; p < 4; p++) acc[g][p] = 0ull;

    for (int ck = 0; ck < 8; ck++) {
        __syncthreads();
        for (int i = tid; i < 64 * 32; i += 256) xs[i] = embt[ck * 2048 + i];
        __syncthreads();
        const float4* W = (const float4*)(g_W0T + (size_t)(ck * 64) * 2048 + jjbase);
        const float* xr = xs + bg * 8;
#pragma unroll 4
        for (int k = 0; k < 64; k++) {
            float4 w = W[(size_t)k * 512];
            unsigned long long wx = pack2(w.x, w.x);
            unsigned long long wy = pack2(w.y, w.y);
            unsigned long long wz = pack2(w.z, w.z);
            unsigned long long ww = pack2(w.w, w.w);
            const unsigned long long* xp = (const unsigned long long*)(xr + k * 32);
#pragma unroll
            for (int p = 0; p < 4; p++) {
                unsigned long long xv = xp[p];
                FMA2(acc[0][p], wx, xv);
                FMA2(acc[1][p], wy, xv);
                FMA2(acc[2][p], wz, xv);
                FMA2(acc[3][p], ww, xv);
            }
        }
    }
#pragma unroll
    for (int g = 0; g < 4; g++) {
        float* dst = g_emb0 + ((size_t)t * 2048 + jjbase + g) * 32 + bg * 8;
#pragma unroll
        for (int p = 0; p < 4; p++) {
            float lo, hi;
            unpack2(acc[g][p], lo, hi);
            *(float2*)(dst + 2 * p) = make_float2(lo, hi);
        }
    }
    GDC_TRIGGER();
}

// ---- Node A: attn (32) || mm0 h0-half (64) || mm1 h1-half (64); all deps from t-1 ----
__global__ __launch_bounds__(256) void step_a_kernel(const float* __restrict__ enc) {
    GDC_WAIT();
    __shared__ float sbuf[2048];
    int cta = blockIdx.x, tid = threadIdx.x;

    if (cta < 64) {
        // mm0 h0-half
        int jx = cta & 7, ks = cta >> 3;
        int j = tid & 63, bg = tid >> 6;
        for (int i = tid; i < 64 * 32; i += 256) sbuf[i] = g_h0T[ks * 2048 + i];
        __syncthreads();
        mm_chunk(g_W0T + (size_t)(1024 + ks * 64) * 2048 + jx * 256, sbuf, j, bg,
                 g_part0 + (size_t)(jx * 16 + 8 + ks) * 8192);
        GDC_TRIGGER();
        return;
    }
    if (cta < 128) {
        // mm1 h1-half
        int c = cta - 64;
        int jx = c & 7, ks = c >> 3;
        int j = tid & 63, bg = tid >> 6;
        for (int i = tid; i < 64 * 32; i += 256) sbuf[i] = g_h1T[ks * 2048 + i];
        __syncthreads();
        mm_chunk(g_W1T + (size_t)(512 + ks * 64) * 2048 + jx * 256, sbuf, j, bg,
                 g_part1 + (size_t)(jx * 16 + 8 + ks) * 8192);
        GDC_TRIGGER();
        return;
    }

    // attention for b = cta - 128
    int b = cta - 128;
    float* q = sbuf;           // 512
    float* sc = sbuf + 512;    // 196
    float* redv = sbuf + 720;  // 16
    int lane = tid & 31, wid = tid >> 5;

    for (int i = tid; i < 512; i += 256) q[i] = g_h1T[i * 32 + b];
    __syncthreads();

    for (int s = wid; s < 196; s += 8) {
        const float* e = enc + ((size_t)b * 196 + s) * 512;
        float a = 0.f;
#pragma unroll
        for (int k = lane; k < 512; k += 32) a = fmaf(q[k], e[k], a);
        a = warp_sum(a);
        if (!lane) sc[s] = a * 0.04419417382415922f;
    }
    __syncthreads();

    float v = (tid < 196) ? sc[tid] : -1e30f;
    float m = v;
#pragma unroll
    for (int o = 16; o; o >>= 1) m = fmaxf(m, __shfl_xor_sync(FULLMASK, m, o));
    if (!lane) redv[wid] = m;
    __syncthreads();
    m = redv[0];
#pragma unroll
    for (int i = 1; i < 8; i++) m = fmaxf(m, redv[i]);
    float ev = (tid < 196) ? expf(v - m) : 0.f;
    float s = warp_sum(ev);
    if (!lane) redv[8 + wid] = s;
    __syncthreads();
    s = 0.f;
#pragma unroll
    for (int i = 0; i < 8; i++) s += redv[8 + i];
    if (tid < 196) sc[tid] = ev / s;
    __syncthreads();

    // ctx: 2 j's per thread
    {
        const float* e = enc + (size_t)b * 196 * 512 + tid;
        float a0 = 0.f, a1 = 0.f;
#pragma unroll 4
        for (int ss = 0; ss < 196; ss++) {
            float w = sc[ss];
            a0 = fmaf(w, e[(size_t)ss * 512], a0);
            a1 = fmaf(w, e[(size_t)ss * 512 + 256], a1);
        }
        g_ctxT[tid * 32 + b] = a0;
        g_ctxT[(tid + 256) * 32 + b] = a1;
    }
    GDC_TRIGGER();
}

// ---- Node R0: wide red0 + inline ctx-dot (64 CTAs, 16K threads) -> h0, c0 ----
__global__ __launch_bounds__(256) void step_red0_kernel(int t) {
    GDC_WAIT();
    int idx = blockIdx.x * 256 + threadIdx.x;  // < 16384
    int j = idx >> 5, b = idx & 31;
    const float* emb0t = g_emb0 + (size_t)t * 2048 * 32;
    float4 bs = ((const float4*)g_b0)[j];
    float s0 = bs.x + emb0t[(j * 4 + 0) * 32 + b];
    float s1 = bs.y + emb0t[(j * 4 + 1) * 32 + b];
    float s2 = bs.z + emb0t[(j * 4 + 2) * 32 + b];
    float s3 = bs.w + emb0t[(j * 4 + 3) * 32 + b];
    reduce_gates_half(g_part0, j, b, s0, s1, s2, s3);
    dot_gates(g_W0T + (size_t)512 * 2048, g_ctxT, j, b, s0, s1, s2, s3);  // ctx half inline
    float gi = sigmoidf_(s0), gf = sigmoidf_(s1);
    float gg = tanhf(s2), go = sigmoidf_(s3);
    int jb = j * 32 + b;
    float c2 = gf * g_c0T[jb] + gi * gg;
    g_c0T[jb] = c2;
    g_h0T[jb] = go * tanhf(c2);
    GDC_TRIGGER();
}

// ---- Node R1: wide red1 + inline h0-dot (64 CTAs) -> h1, c1, hs splits ----
__global__ __launch_bounds__(256) void step_red1_kernel(int t) {
    GDC_WAIT();
    int idx = blockIdx.x * 256 + threadIdx.x;  // < 16384
    int j = idx >> 5, b = idx & 31;
    float4 bs = ((const float4*)g_b1)[j];
    float s0 = bs.x, s1 = bs.y, s2 = bs.z, s3 = bs.w;
    reduce_gates_half(g_part1, j, b, s0, s1, s2, s3);
    dot_gates(g_W1T, g_h0T, j, b, s0, s1, s2, s3);  // h0 half inline (h0(t) just written)
    float gi = sigmoidf_(s0), gf = sigmoidf_(s1);
    float gg = tanhf(s2), go = sigmoidf_(s3);
    int jb = j * 32 + b;
    float c2 = gf * g_c1T[jb] + gi * gg;
    g_c1T[jb] = c2;
    float h = go * tanhf(c2);
    g_h1T[jb] = h;
    __nv_bfloat16 hh = __float2bfloat16(h);
    size_t m = (size_t)(t * 32 + b) * 512 + j;
    g_hsH[m] = hh;
    g_hsL[m] = __float2bfloat16(h - __bfloat162float(hh));
    GDC_TRIGGER();
}

// ---------------- tensor-core FC via mma.sync bf16 split ----------------
__global__ __launch_bounds__(256, 1) void fc_mma_kernel(const float* __restrict__ fcb,
                                                        float* __restrict__ out) {
    GDC_WAIT();
    extern __shared__ char smem[];
    uint32_t sbase = smem_to_u32(smem);
    int tid = threadIdx.x, lane = tid & 31, wid = tid >> 5;
    int mb = blockIdx.y * 128, nb = blockIdx.x * 128;
    int warp_m = (wid & 1) * 64, warp_n = (wid >> 1) * 32;

    float acc[4][4][4];
#pragma unroll
    for (int mi = 0; mi < 4; mi++)
#pragma unroll
        for (int nj = 0; nj < 4; nj++)
#pragma unroll
            for (int r = 0; r < 4; r++) acc[mi][nj][r] = 0.f;

    for (int kc = 0; kc < 8; kc++) {
        __syncthreads();
#pragma unroll
        for (int it = 0; it < 16; it++) {
            int s = tid + it * 256;                 // < 4096
            int tile = s >> 10, r = (s >> 3) & 127, c = s & 7;
            const __nv_bfloat16* g;
            if (tile == 0)      g = g_hsH + (size_t)(mb + r) * 512;
            else if (tile == 1) g = g_hsL + (size_t)(mb + r) * 512;
            else if (tile == 2) g = g_fcwH + (size_t)(nb + r) * 512;
            else                g = g_fcwL + (size_t)(nb + r) * 512;
            uint4 v = *(const uint4*)(g + kc * 64 + c * 8);
            uint32_t off = (uint32_t)(r * 128 + c * 16);
            off ^= (off >> 3) & 0x70;
            *(uint4*)(smem + tile * 16384 + off) = v;
        }
        __syncthreads();

#pragma unroll
        for (int ka = 0; ka < 4; ka++) {
            uint32_t a_hi[4][4], a_lo[4][4], b_hi[4][2], b_lo[4][2];
            int rA = warp_m + (lane & 15);
            int sA = ka * 2 + (lane >> 4);
#pragma unroll
            for (int mi = 0; mi < 4; mi++) {
                uint32_t off = (uint32_t)((rA + mi * 16) * 128 + sA * 16);
                off ^= (off >> 3) & 0x70;
                LDMATRIX_X4(a_hi[mi][0], a_hi[mi][1], a_hi[mi][2], a_hi[mi][3], sbase + off);
                LDMATRIX_X4(a_lo[mi][0], a_lo[mi][1], a_lo[mi][2], a_lo[mi][3],
                            sbase + 16384 + off);
            }
            int rB = warp_n + (lane & 7);
            int sB = ka * 2 + ((lane >> 3) & 1);
#pragma unroll
            for (int nj = 0; nj < 4; nj++) {
                uint32_t off = (uint32_t)((rB + nj * 8) * 128 + sB * 16);
                off ^= (off >> 3) & 0x70;
                LDMATRIX_X2(b_hi[nj][0], b_hi[nj][1], sbase + 32768 + off);
                LDMATRIX_X2(b_lo[nj][0], b_lo[nj][1], sbase + 49152 + off);
            }
#pragma unroll
            for (int mi = 0; mi < 4; mi++)
#pragma unroll
                for (int nj = 0; nj < 4; nj++) {
                    MMA_BF16(acc[mi][nj], a_hi[mi], b_hi[nj]);
                    MMA_BF16(acc[mi][nj], a_hi[mi], b_lo[nj]);
                    MMA_BF16(acc[mi][nj], a_lo[mi], b_hi[nj]);
                }
        }
    }

    int g = lane >> 2, q = lane & 3;
#pragma unroll
    for (int mi = 0; mi < 4; mi++) {
#pragma unroll
        for (int nj = 0; nj < 4; nj++) {
            int m = mb + warp_m + mi * 16 + g;
            int n = nb + warp_n + nj * 8 + q * 2;
            float2 bb = *(const float2*)(fcb + n);
            *(float2*)(out + (size_t)m * 32000 + n) =
                make_float2(acc[mi][nj][0] + bb.x, acc[mi][nj][1] + bb.y);
            *(float2*)(out + (size_t)(m + 8) * 32000 + n) =
                make_float2(acc[mi][nj][2] + bb.x, acc[mi][nj][3] + bb.y);
        }
    }
}

// ---------------- PDL launch helper ----------------
template <typename K, typename... Args>
static void launch_pdl(K kernel, dim3 grid, dim3 block, size_t smem, Args... args) {
    cudaLaunchConfig_t cfg = {};
    cfg.gridDim = grid;
    cfg.blockDim = block;
    cfg.dynamicSmemBytes = smem;
    cfg.stream = 0;
    cudaLaunchAttribute at[1];
    at[0].id = cudaLaunchAttributeProgrammaticStreamSerialization;
    at[0].val.programmaticStreamSerializationAllowed = 1;
    cfg.attrs = at;
    cfg.numAttrs = 1;
    cudaLaunchKernelEx(&cfg, kernel, args...);
}

// ---------------- launch ----------------
extern "C" void kernel_launch(void* const* d_in, const int* in_sizes, int n_in,
                              void* d_out, int out_size) {
    (void)in_sizes; (void)n_in; (void)out_size;
    const float* features = (const float*)d_in[0];
    const int*   captions = (const int*)d_in[1];
    const float* enc   = (const float*)d_in[3];
    const float* table = (const float*)d_in[4];
    const float* ft1w  = (const float*)d_in[5];
    const float* ft1b  = (const float*)d_in[6];
    const float* ft2w  = (const float*)d_in[7];
    const float* ft2b  = (const float*)d_in[8];
    const float* wih0  = (const float*)d_in[9];
    const float* whh0  = (const float*)d_in[10];
    const float* bih0  = (const float*)d_in[11];
    const float* bhh0  = (const float*)d_in[12];
    const float* wih1  = (const float*)d_in[13];
    const float* whh1  = (const float*)d_in[14];
    const float* bih1  = (const float*)d_in[15];
    const float* bhh1  = (const float*)d_in[16];
    const float* fcw   = (const float*)d_in[17];
    const float* fcb   = (const float*)d_in[18];
    float* out = (float*)d_out;

    static int smem_set = 0;
    if (!smem_set) {
        cudaFuncSetAttribute(fc_mma_kernel, cudaFuncAttributeMaxDynamicSharedMemorySize, 65536);
        smem_set = 1;
    }

    launch_pdl(prepW0_kernel, dim3(64, 48), dim3(256), 0, wih0, whh0);
    launch_pdl(prepW1_kernel, dim3(64, 32), dim3(256), 0, wih1, whh1);
    launch_pdl(prepB_kernel, dim3(8), dim3(256), 0, bih0, bhh0, bih1, bhh1);
    launch_pdl(embed_kernel, dim3(4096), dim3(256), 0, captions, table);
    launch_pdl(feat1_kernel, dim3(2048), dim3(256), 0, features, ft1w, ft1b);
    launch_pdl(feat2_kernel, dim3(2048), dim3(256), 0, ft2w, ft2b);
    launch_pdl(splitW_kernel, dim3(16000), dim3(256), 0, fcw);
    launch_pdl(lstm0_pre_kernel, dim3(8, 64), dim3(256), 0);

    for (int t = 0; t < 64; t++) {
        launch_pdl(step_a_kernel, dim3(160), dim3(256), 0, enc);
        launch_pdl(step_red0_kernel, dim3(64), dim3(256), 0, t);
        launch_pdl(step_red1_kernel, dim3(64), dim3(256), 0, t);
    }

    launch_pdl(fc_mma_kernel, dim3(250, 16), dim3(256), (size_t)65536, fcb, out);
}

// round 16
// speedup vs baseline: 1.6124x; 1.6124x over previous
#include <cuda_runtime.h>
#include <cuda_bf16.h>
#include <math.h>
#include <stdint.h>

#define FULLMASK 0xffffffffu

// ---------------- persistent device scratch ----------------
__device__ float g_W0T[1536 * 2048];      // layer0 weights [k][j*4+gate] (k: emb|ctx|h0)
__device__ float g_W1T[1024 * 2048];      // layer1 weights [k][j*4+gate] (k: h0|h1)
__device__ float g_b0[2048];
__device__ float g_b1[2048];
__device__ float g_embT[64 * 512 * 32];   // embeddings [t][k][b]
__device__ float g_emb0[64 * 2048 * 32];  // precomputed emb @ W0e, [t][jj][b]
__device__ float g_f1[32 * 512];
__device__ float g_h0T[512 * 32];         // h0 state [j][b]
__device__ float g_h1T[512 * 32];         // h1 state [j][b]
__device__ float g_c0T[512 * 32];
__device__ float g_c1T[512 * 32];
__device__ float g_ctxT[512 * 32];
__device__ float g_part0[128 * 8192];     // [jx*16+ks][(jloc*4+g)*32+b] (ks0-7 ctx, 8-15 h0)
__device__ float g_part1[128 * 8192];     // (ks0-7 h0-half, 8-15 h1-half)
// bf16 split operands for tensor-core FC
__device__ __align__(16) __nv_bfloat16 g_hsH[2048 * 512];
__device__ __align__(16) __nv_bfloat16 g_hsL[2048 * 512];
__device__ __align__(16) __nv_bfloat16 g_fcwH[32000 * 512];
__device__ __align__(16) __nv_bfloat16 g_fcwL[32000 * 512];

// single extern shared symbol (typed casts at use sites)
extern __shared__ char g_smem_raw[];

// ---------------- helpers ----------------
static __device__ __forceinline__ float sigmoidf_(float x) { return 1.f / (1.f + expf(-x)); }

static __device__ __forceinline__ float warp_sum(float v) {
#pragma unroll
    for (int o = 16; o; o >>= 1) v += __shfl_xor_sync(FULLMASK, v, o);
    return v;
}

static __device__ __forceinline__ unsigned long long pack2(float lo, float hi) {
    unsigned long long r;
    asm("mov.b64 %0, {%1, %2};" : "=l"(r) : "f"(lo), "f"(hi));
    return r;
}
static __device__ __forceinline__ void unpack2(unsigned long long v, float& lo, float& hi) {
    asm("mov.b64 {%0, %1}, %2;" : "=f"(lo), "=f"(hi) : "l"(v));
}
#define FMA2(acc, a, b) asm("fma.rn.f32x2 %0, %1, %2, %0;" : "+l"(acc) : "l"(a), "l"(b))

static __device__ __forceinline__ uint32_t smem_to_u32(const void* p) {
    uint32_t a;
    asm("{ .reg .u64 tmp; cvta.to.shared.u64 tmp, %1; cvt.u32.u64 %0, tmp; }" : "=r"(a) : "l"(p));
    return a;
}

#define GDC_WAIT()    asm volatile("griddepcontrol.wait;" ::: "memory")
#define GDC_TRIGGER() asm volatile("griddepcontrol.launch_dependents;" ::: "memory")

#define LDMATRIX_X4(r0, r1, r2, r3, addr) \
    asm volatile("ldmatrix.sync.aligned.m8n8.x4.shared.b16 {%0,%1,%2,%3}, [%4];" \
                 : "=r"(r0), "=r"(r1), "=r"(r2), "=r"(r3) : "r"(addr))
#define LDMATRIX_X2(r0, r1, addr) \
    asm volatile("ldmatrix.sync.aligned.m8n8.x2.shared.b16 {%0,%1}, [%2];" \
                 : "=r"(r0), "=r"(r1) : "r"(addr))

#define MMA_BF16(c, a, b) \
    asm volatile("mma.sync.aligned.m16n8k16.row.col.f32.bf16.bf16.f32 " \
                 "{%0,%1,%2,%3}, {%4,%5,%6,%7}, {%8,%9}, {%0,%1,%2,%3};" \
                 : "+f"((c)[0]), "+f"((c)[1]), "+f"((c)[2]), "+f"((c)[3]) \
                 : "r"((a)[0]), "r"((a)[1]), "r"((a)[2]), "r"((a)[3]), \
                   "r"((b)[0]), "r"((b)[1]))

// ---------------- GEMM partial: 64-k-chunk from GLOBAL weights ----------------
static __device__ __forceinline__ void mm_chunk(const float* __restrict__ W0,
                                                const float* xs, int j, int bg,
                                                float* __restrict__ dst_slot) {
    const float4* W = (const float4*)(W0 + j * 4);
    unsigned long long acc[4][4];
#pragma unroll
    for (int g = 0; g < 4; g++)
#pragma unroll
        for (int p = 0; p < 4; p++) acc[g][p] = 0ull;
    const float* xr = xs + bg * 8;
#pragma unroll 8
    for (int k = 0; k < 64; k++) {
        float4 w = W[(size_t)k * 512];
        unsigned long long wx = pack2(w.x, w.x);
        unsigned long long wy = pack2(w.y, w.y);
        unsigned long long wz = pack2(w.z, w.z);
        unsigned long long ww = pack2(w.w, w.w);
        const unsigned long long* xp = (const unsigned long long*)(xr + k * 32);
#pragma unroll
        for (int p = 0; p < 4; p++) {
            unsigned long long xv = xp[p];
            FMA2(acc[0][p], wx, xv);
            FMA2(acc[1][p], wy, xv);
            FMA2(acc[2][p], wz, xv);
            FMA2(acc[3][p], ww, xv);
        }
    }
    float* dst = dst_slot + (j * 4) * 32 + bg * 8;
#pragma unroll
    for (int g = 0; g < 4; g++)
#pragma unroll
        for (int p = 0; p < 4; p++) {
            float lo, hi;
            unpack2(acc[g][p], lo, hi);
            *(float2*)(dst + g * 32 + 2 * p) = make_float2(lo, hi);
        }
}

// ---------------- GEMM partial: 64-k-chunk from SMEM weights (preloaded) ----------------
static __device__ __forceinline__ void mm_chunk_s(const float* ws,   // [k][256] floats
                                                  const float* xs, int j, int bg,
                                                  float* __restrict__ dst_slot) {
    const float4* W = (const float4*)ws;   // index k*64 + j
    unsigned long long acc[4][4];
#pragma unroll
    for (int g = 0; g < 4; g++)
#pragma unroll
        for (int p = 0; p < 4; p++) acc[g][p] = 0ull;
    const float* xr = xs + bg * 8;
#pragma unroll 8
    for (int k = 0; k < 64; k++) {
        float4 w = W[k * 64 + j];
        unsigned long long wx = pack2(w.x, w.x);
        unsigned long long wy = pack2(w.y, w.y);
        unsigned long long wz = pack2(w.z, w.z);
        unsigned long long ww = pack2(w.w, w.w);
        const unsigned long long* xp = (const unsigned long long*)(xr + k * 32);
#pragma unroll
        for (int p = 0; p < 4; p++) {
            unsigned long long xv = xp[p];
            FMA2(acc[0][p], wx, xv);
            FMA2(acc[1][p], wy, xv);
            FMA2(acc[2][p], wz, xv);
            FMA2(acc[3][p], ww, xv);
        }
    }
    float* dst = dst_slot + (j * 4) * 32 + bg * 8;
#pragma unroll
    for (int g = 0; g < 4; g++)
#pragma unroll
        for (int p = 0; p < 4; p++) {
            float lo, hi;
            unpack2(acc[g][p], lo, hi);
            *(float2*)(dst + g * 32 + 2 * p) = make_float2(lo, hi);
        }
}

// gate-quad reduction (coalesced: warp spans b) over the 16 part slots
static __device__ __forceinline__ void reduce_gates(const float* __restrict__ part,
                                                    int j, int b,
                                                    float& s0, float& s1,
                                                    float& s2, float& s3) {
    const float* base = part + (size_t)(j >> 6) * 16 * 8192 + ((j & 63) * 4) * 32 + b;
#pragma unroll
    for (int k2 = 0; k2 < 16; k2++) {
        const float* p = base + (size_t)k2 * 8192;
        s0 += p[0];
        s1 += p[32];
        s2 += p[64];
        s3 += p[96];
    }
}

// ---------------- weight preprocessing (tiled transpose) ----------------
__global__ __launch_bounds__(256) void prepW0_kernel(const float* __restrict__ wih0,
                                                     const float* __restrict__ whh0) {
    GDC_WAIT();
    __shared__ float tile[32][33];
    int jj0 = blockIdx.x * 32;
    int k0 = blockIdx.y * 32;
    int tx = threadIdx.x & 31, ty = threadIdx.x >> 5;
    for (int jjl = ty; jjl < 32; jjl += 8) {
        int jj = jj0 + jjl;
        int j = jj >> 2, g = jj & 3;
        int row = g * 512 + j;
        int k = k0 + tx;
        float v = (k < 1024) ? wih0[row * 1024 + k] : whh0[row * 512 + (k - 1024)];
        tile[jjl][tx] = v;
    }
    __syncthreads();
    for (int kl = ty; kl < 32; kl += 8)
        g_W0T[(size_t)(k0 + kl) * 2048 + jj0 + tx] = tile[tx][kl];
    GDC_TRIGGER();
}

__global__ __launch_bounds__(256) void prepW1_kernel(const float* __restrict__ wih1,
                                                     const float* __restrict__ whh1) {
    GDC_WAIT();
    __shared__ float tile[32][33];
    int jj0 = blockIdx.x * 32;
    int k0 = blockIdx.y * 32;
    int tx = threadIdx.x & 31, ty = threadIdx.x >> 5;
    for (int jjl = ty; jjl < 32; jjl += 8) {
        int jj = jj0 + jjl;
        int j = jj >> 2, g = jj & 3;
        int row = g * 512 + j;
        int k = k0 + tx;
        float v = (k < 512) ? wih1[row * 512 + k] : whh1[row * 512 + (k - 512)];
        tile[jjl][tx] = v;
    }
    __syncthreads();
    for (int kl = ty; kl < 32; kl += 8)
        g_W1T[(size_t)(k0 + kl) * 2048 + jj0 + tx] = tile[tx][kl];
    GDC_TRIGGER();
}

__global__ __launch_bounds__(256) void prepB_kernel(const float* __restrict__ bih0,
                                                    const float* __restrict__ bhh0,
                                                    const float* __restrict__ bih1,
                                                    const float* __restrict__ bhh1) {
    GDC_WAIT();
    int jj = blockIdx.x * 256 + threadIdx.x;
    int j = jj >> 2, g = jj & 3;
    int row = g * 512 + j;
    g_b0[jj] = bih0[row] + bhh0[row];
    g_b1[jj] = bih1[row] + bhh1[row];
    GDC_TRIGGER();
}

__global__ __launch_bounds__(256) void splitW_kernel(const float* __restrict__ fcw) {
    GDC_WAIT();
    int idx = (blockIdx.x * 256 + threadIdx.x) * 4;   // < 32000*512
    float4 v = *(const float4*)(fcw + idx);
    __nv_bfloat16 h0 = __float2bfloat16(v.x), h1 = __float2bfloat16(v.y);
    __nv_bfloat16 h2 = __float2bfloat16(v.z), h3 = __float2bfloat16(v.w);
    __nv_bfloat162 hA, hB, lA, lB;
    hA.x = h0; hA.y = h1; hB.x = h2; hB.y = h3;
    lA.x = __float2bfloat16(v.x - __bfloat162float(h0));
    lA.y = __float2bfloat16(v.y - __bfloat162float(h1));
    lB.x = __float2bfloat16(v.z - __bfloat162float(h2));
    lB.y = __float2bfloat16(v.w - __bfloat162float(h3));
    *(__nv_bfloat162*)(g_fcwH + idx) = hA;
    *(__nv_bfloat162*)(g_fcwH + idx + 2) = hB;
    *(__nv_bfloat162*)(g_fcwL + idx) = lA;
    *(__nv_bfloat162*)(g_fcwL + idx + 2) = lB;
    GDC_TRIGGER();
}

// ---------------- embedding gather: embT[t][k][b] ----------------
__global__ __launch_bounds__(256) void embed_kernel(const int* __restrict__ cap,
                                                    const float* __restrict__ table) {
    GDC_WAIT();
    int idx = blockIdx.x * 256 + threadIdx.x;
    int b = idx >> 15;
    int t = (idx >> 9) & 63;
    int k = idx & 511;
    int tok = cap[b * 64 + t];
    g_embT[(t * 512 + k) * 32 + b] = table[(size_t)tok * 512 + k];
    GDC_TRIGGER();
}

// ---------------- feature MLP ----------------
__global__ __launch_bounds__(256) void feat1_kernel(const float* __restrict__ features,
                                                    const float* __restrict__ w,
                                                    const float* __restrict__ bias) {
    GDC_WAIT();
    int gid = blockIdx.x * 8 + (threadIdx.x >> 5);
    int lane = threadIdx.x & 31;
    int b = gid >> 9, j = gid & 511;
    const float* fr = features + b * 2048;
    const float* wr = w + j * 2048;
    float a = 0.f;
    for (int k = lane; k < 2048; k += 32) a = fmaf(fr[k], wr[k], a);
    a = warp_sum(a);
    if (!lane) g_f1[gid] = fmaxf(a + bias[j], 0.f);
    GDC_TRIGGER();
}

__global__ __launch_bounds__(256) void feat2_kernel(const float* __restrict__ w,
                                                    const float* __restrict__ bias) {
    GDC_WAIT();
    int gid = blockIdx.x * 8 + (threadIdx.x >> 5);
    int lane = threadIdx.x & 31;
    int b = gid >> 9, j = gid & 511;
    const float* fr = g_f1 + b * 512;
    const float* wr = w + j * 512;
    float a = 0.f;
    for (int k = lane; k < 512; k += 32) a = fmaf(fr[k], wr[k], a);
    a = warp_sum(a);
    if (!lane) {
        float v = a + bias[j];
        int jb = j * 32 + b;
        g_h0T[jb] = v;
        g_h1T[jb] = v;
        g_c0T[jb] = v;
        g_c1T[jb] = v;
    }
    GDC_TRIGGER();
}

// ---------------- precompute emb @ W0e for all t ----------------
__global__ __launch_bounds__(256) void lstm0_pre_kernel() {
    GDC_WAIT();
    __shared__ float xs[64 * 32];
    int jx = blockIdx.x, t = blockIdx.y;
    int tid = threadIdx.x;
    int j = tid & 63, bg = tid >> 6;
    int jjbase = (jx * 64 + j) * 4;
    const float* embt = g_embT + (size_t)t * 512 * 32;

    unsigned long long acc[4][4];
#pragma unroll
    for (int g = 0; g < 4; g++)
#pragma unroll
        for (int p = 0; p < 4; p++) acc[g][p] = 0ull;

    for (int ck = 0; ck < 8; ck++) {
        __syncthreads();
        for (int i = tid; i < 64 * 32; i += 256) xs[i] = embt[ck * 2048 + i];
        __syncthreads();
        const float4* W = (const float4*)(g_W0T + (size_t)(ck * 64) * 2048 + jjbase);
        const float* xr = xs + bg * 8;
#pragma unroll 4
        for (int k = 0; k < 64; k++) {
            float4 w = W[(size_t)k * 512];
            unsigned long long wx = pack2(w.x, w.x);
            unsigned long long wy = pack2(w.y, w.y);
            unsigned long long wz = pack2(w.z, w.z);
            unsigned long long ww = pack2(w.w, w.w);
            const unsigned long long* xp = (const unsigned long long*)(xr + k * 32);
#pragma unroll
            for (int p = 0; p < 4; p++) {
                unsigned long long xv = xp[p];
                FMA2(acc[0][p], wx, xv);
                FMA2(acc[1][p], wy, xv);
                FMA2(acc[2][p], wz, xv);
                FMA2(acc[3][p], ww, xv);
            }
        }
    }
#pragma unroll
    for (int g = 0; g < 4; g++) {
        float* dst = g_emb0 + ((size_t)t * 2048 + jjbase + g) * 32 + bg * 8;
#pragma unroll
        for (int p = 0; p < 4; p++) {
            float lo, hi;
            unpack2(acc[g][p], lo, hi);
            *(float2*)(dst + 2 * p) = make_float2(lo, hi);
        }
    }
    GDC_TRIGGER();
}

// ---- Node A: attn (32) || mm0 h0-half (64) || mm1 h1-half (64); all deps from t-1 ----
__global__ __launch_bounds__(256) void step_a_kernel(const float* __restrict__ enc) {
    GDC_WAIT();
    GDC_TRIGGER();                 // early: dependents prefetch while we compute
    __shared__ float sbuf[2048];
    int cta = blockIdx.x, tid = threadIdx.x;

    if (cta < 64) {
        // mm0 h0-half
        int jx = cta & 7, ks = cta >> 3;
        int j = tid & 63, bg = tid >> 6;
        for (int i = tid; i < 64 * 32; i += 256) sbuf[i] = g_h0T[ks * 2048 + i];
        __syncthreads();
        mm_chunk(g_W0T + (size_t)(1024 + ks * 64) * 2048 + jx * 256, sbuf, j, bg,
                 g_part0 + (size_t)(jx * 16 + 8 + ks) * 8192);
        return;
    }
    if (cta < 128) {
        // mm1 h1-half
        int c = cta - 64;
        int jx = c & 7, ks = c >> 3;
        int j = tid & 63, bg = tid >> 6;
        for (int i = tid; i < 64 * 32; i += 256) sbuf[i] = g_h1T[ks * 2048 + i];
        __syncthreads();
        mm_chunk(g_W1T + (size_t)(512 + ks * 64) * 2048 + jx * 256, sbuf, j, bg,
                 g_part1 + (size_t)(jx * 16 + 8 + ks) * 8192);
        return;
    }

    // attention for b = cta - 128
    int b = cta - 128;
    float* q = sbuf;           // 512
    float* sc = sbuf + 512;    // 196
    float* redv = sbuf + 720;  // 16
    int lane = tid & 31, wid = tid >> 5;

    for (int i = tid; i < 512; i += 256) q[i] = g_h1T[i * 32 + b];
    __syncthreads();

    for (int s = wid; s < 196; s += 8) {
        const float* e = enc + ((size_t)b * 196 + s) * 512;
        float a = 0.f;
#pragma unroll
        for (int k = lane; k < 512; k += 32) a = fmaf(q[k], e[k], a);
        a = warp_sum(a);
        if (!lane) sc[s] = a * 0.04419417382415922f;
    }
    __syncthreads();

    float v = (tid < 196) ? sc[tid] : -1e30f;
    float m = v;
#pragma unroll
    for (int o = 16; o; o >>= 1) m = fmaxf(m, __shfl_xor_sync(FULLMASK, m, o));
    if (!lane) redv[wid] = m;
    __syncthreads();
    m = redv[0];
#pragma unroll
    for (int i = 1; i < 8; i++) m = fmaxf(m, redv[i]);
    float ev = (tid < 196) ? expf(v - m) : 0.f;
    float s = warp_sum(ev);
    if (!lane) redv[8 + wid] = s;
    __syncthreads();
    s = 0.f;
#pragma unroll
    for (int i = 0; i < 8; i++) s += redv[8 + i];
    if (tid < 196) sc[tid] = ev / s;
    __syncthreads();

    // ctx: 2 j's per thread
    {
        const float* e = enc + (size_t)b * 196 * 512 + tid;
        float a0 = 0.f, a1 = 0.f;
#pragma unroll 4
        for (int ss = 0; ss < 196; ss++) {
            float w = sc[ss];
            a0 = fmaf(w, e[(size_t)ss * 512], a0);
            a1 = fmaf(w, e[(size_t)ss * 512 + 256], a1);
        }
        g_ctxT[tid * 32 + b] = a0;
        g_ctxT[(tid + 256) * 32 + b] = a1;
    }
}

// ---- Node B: mm0 ctx-half (64 CTAs); weights preloaded to smem BEFORE wait ----
__global__ __launch_bounds__(256) void step_b_kernel() {
    float* ws = (float*)g_smem_raw;          // 64*256 floats (64 KB)
    float* xs = (float*)g_smem_raw + 16384;  // 2048 floats
    int cta = blockIdx.x, tid = threadIdx.x;
    int jx = cta & 7, ks = cta >> 3;
    int j = tid & 63, bg = tid >> 6;

    // PRE-WAIT: static weight slice -> smem (overlaps predecessor via early trigger)
    {
        const float* Wg = g_W0T + (size_t)(512 + ks * 64) * 2048 + jx * 256;
#pragma unroll
        for (int it = 0; it < 16; it++) {
            int i = tid + it * 256;          // < 4096 float4
            int k = i >> 6, c = i & 63;
            ((float4*)ws)[k * 64 + c] = *(const float4*)(Wg + (size_t)k * 2048 + c * 4);
        }
    }
    GDC_WAIT();
    GDC_TRIGGER();
    for (int i = tid; i < 2048; i += 256) xs[i] = g_ctxT[ks * 2048 + i];
    __syncthreads();
    mm_chunk_s(ws, xs, j, bg, g_part0 + (size_t)(jx * 16 + ks) * 8192);
}

// ---- Node C: wide red0 (64 CTAs, 16K threads) -> h0, c0; static loads pre-wait ----
__global__ __launch_bounds__(256) void step_red0_kernel(int t) {
    int idx = blockIdx.x * 256 + threadIdx.x;  // < 16384
    int j = idx >> 5, b = idx & 31;
    const float* emb0t = g_emb0 + (size_t)t * 2048 * 32;
    float4 bs = ((const float4*)g_b0)[j];
    float e0 = emb0t[(j * 4 + 0) * 32 + b];
    float e1 = emb0t[(j * 4 + 1) * 32 + b];
    float e2 = emb0t[(j * 4 + 2) * 32 + b];
    float e3 = emb0t[(j * 4 + 3) * 32 + b];
    GDC_WAIT();
    GDC_TRIGGER();
    float s0 = bs.x + e0, s1 = bs.y + e1, s2 = bs.z + e2, s3 = bs.w + e3;
    reduce_gates(g_part0, j, b, s0, s1, s2, s3);
    float gi = sigmoidf_(s0), gf = sigmoidf_(s1);
    float gg = tanhf(s2), go = sigmoidf_(s3);
    int jb = j * 32 + b;
    float c2 = gf * g_c0T[jb] + gi * gg;
    g_c0T[jb] = c2;
    g_h0T[jb] = go * tanhf(c2);
}

// ---- Node D: mm1 h0-half (64 CTAs); weights preloaded to smem BEFORE wait ----
__global__ __launch_bounds__(256) void step_d_kernel() {
    float* ws = (float*)g_smem_raw;
    float* xs = (float*)g_smem_raw + 16384;
    int cta = blockIdx.x, tid = threadIdx.x;
    int jx = cta & 7, ks = cta >> 3;
    int j = tid & 63, bg = tid >> 6;

    {
        const float* Wg = g_W1T + (size_t)(ks * 64) * 2048 + jx * 256;
#pragma unroll
        for (int it = 0; it < 16; it++) {
            int i = tid + it * 256;
            int k = i >> 6, c = i & 63;
            ((float4*)ws)[k * 64 + c] = *(const float4*)(Wg + (size_t)k * 2048 + c * 4);
        }
    }
    GDC_WAIT();
    GDC_TRIGGER();
    for (int i = tid; i < 2048; i += 256) xs[i] = g_h0T[ks * 2048 + i];
    __syncthreads();
    mm_chunk_s(ws, xs, j, bg, g_part1 + (size_t)(jx * 16 + ks) * 8192);
}

// ---- Node E: wide red1 (64 CTAs) -> h1, c1, hs splits ----
__global__ __launch_bounds__(256) void step_red1_kernel(int t) {
    int idx = blockIdx.x * 256 + threadIdx.x;  // < 16384
    int j = idx >> 5, b = idx & 31;
    float4 bs = ((const float4*)g_b1)[j];
    GDC_WAIT();
    GDC_TRIGGER();
    float s0 = bs.x, s1 = bs.y, s2 = bs.z, s3 = bs.w;
    reduce_gates(g_part1, j, b, s0, s1, s2, s3);
    float gi = sigmoidf_(s0), gf = sigmoidf_(s1);
    float gg = tanhf(s2), go = sigmoidf_(s3);
    int jb = j * 32 + b;
    float c2 = gf * g_c1T[jb] + gi * gg;
    g_c1T[jb] = c2;
    float h = go * tanhf(c2);
    g_h1T[jb] = h;
    __nv_bfloat16 hh = __float2bfloat16(h);
    size_t m = (size_t)(t * 32 + b) * 512 + j;
    g_hsH[m] = hh;
    g_hsL[m] = __float2bfloat16(h - __bfloat162float(hh));
}

// ---------------- tensor-core FC via mma.sync bf16 split ----------------
__global__ __launch_bounds__(256, 1) void fc_mma_kernel(const float* __restrict__ fcb,
                                                        float* __restrict__ out) {
    GDC_WAIT();
    char* smem = g_smem_raw;
    uint32_t sbase = smem_to_u32(smem);
    int tid = threadIdx.x, lane = tid & 31, wid = tid >> 5;
    int mb = blockIdx.y * 128, nb = blockIdx.x * 128;
    int warp_m = (wid & 1) * 64, warp_n = (wid >> 1) * 32;

    float acc[4][4][4];
#pragma unroll
    for (int mi = 0; mi < 4; mi++)
#pragma unroll
        for (int nj = 0; nj < 4; nj++)
#pragma unroll
            for (int r = 0; r < 4; r++) acc[mi][nj][r] = 0.f;

    for (int kc = 0; kc < 8; kc++) {
        __syncthreads();
#pragma unroll
        for (int it = 0; it < 16; it++) {
            int s = tid + it * 256;                 // < 4096
            int tile = s >> 10, r = (s >> 3) & 127, c = s & 7;
            const __nv_bfloat16* g;
            if (tile == 0)      g = g_hsH + (size_t)(mb + r) * 512;
            else if (tile == 1) g = g_hsL + (size_t)(mb + r) * 512;
            else if (tile == 2) g = g_fcwH + (size_t)(nb + r) * 512;
            else                g = g_fcwL + (size_t)(nb + r) * 512;
            uint4 v = *(const uint4*)(g + kc * 64 + c * 8);
            uint32_t off = (uint32_t)(r * 128 + c * 16);
            off ^= (off >> 3) & 0x70;
            *(uint4*)(smem + tile * 16384 + off) = v;
        }
        __syncthreads();

#pragma unroll
        for (int ka = 0; ka < 4; ka++) {
            uint32_t a_hi[4][4], a_lo[4][4], b_hi[4][2], b_lo[4][2];
            int rA = warp_m + (lane & 15);
            int sA = ka * 2 + (lane >> 4);
#pragma unroll
            for (int mi = 0; mi < 4; mi++) {
                uint32_t off = (uint32_t)((rA + mi * 16) * 128 + sA * 16);
                off ^= (off >> 3) & 0x70;
                LDMATRIX_X4(a_hi[mi][0], a_hi[mi][1], a_hi[mi][2], a_hi[mi][3], sbase + off);
                LDMATRIX_X4(a_lo[mi][0], a_lo[mi][1], a_lo[mi][2], a_lo[mi][3],
                            sbase + 16384 + off);
            }
            int rB = warp_n + (lane & 7);
            int sB = ka * 2 + ((lane >> 3) & 1);
#pragma unroll
            for (int nj = 0; nj < 4; nj++) {
                uint32_t off = (uint32_t)((rB + nj * 8) * 128 + sB * 16);
                off ^= (off >> 3) & 0x70;
                LDMATRIX_X2(b_hi[nj][0], b_hi[nj][1], sbase + 32768 + off);
                LDMATRIX_X2(b_lo[nj][0], b_lo[nj][1], sbase + 49152 + off);
            }
#pragma unroll
            for (int mi = 0; mi < 4; mi++)
#pragma unroll
                for (int nj = 0; nj < 4; nj++) {
                    MMA_BF16(acc[mi][nj], a_hi[mi], b_hi[nj]);
                    MMA_BF16(acc[mi][nj], a_hi[mi], b_lo[nj]);
                    MMA_BF16(acc[mi][nj], a_lo[mi], b_hi[nj]);
                }
        }
    }

    int g = lane >> 2, q = lane & 3;
#pragma unroll
    for (int mi = 0; mi < 4; mi++) {
#pragma unroll
        for (int nj = 0; nj < 4; nj++) {
            int m = mb + warp_m + mi * 16 + g;
            int n = nb + warp_n + nj * 8 + q * 2;
            float2 bb = *(const float2*)(fcb + n);
            *(float2*)(out + (size_t)m * 32000 + n) =
                make_float2(acc[mi][nj][0] + bb.x, acc[mi][nj][1] + bb.y);
            *(float2*)(out + (size_t)(m + 8) * 32000 + n) =
                make_float2(acc[mi][nj][2] + bb.x, acc[mi][nj][3] + bb.y);
        }
    }
}

// ---------------- PDL launch helper ----------------
template <typename K, typename... Args>
static void launch_pdl(K kernel, dim3 grid, dim3 block, size_t smem, Args... args) {
    cudaLaunchConfig_t cfg = {};
    cfg.gridDim = grid;
    cfg.blockDim = block;
    cfg.dynamicSmemBytes = smem;
    cfg.stream = 0;
    cudaLaunchAttribute at[1];
    at[0].id = cudaLaunchAttributeProgrammaticStreamSerialization;
    at[0].val.programmaticStreamSerializationAllowed = 1;
    cfg.attrs = at;
    cfg.numAttrs = 1;
    cudaLaunchKernelEx(&cfg, kernel, args...);
}

// ---------------- launch ----------------
extern "C" void kernel_launch(void* const* d_in, const int* in_sizes, int n_in,
                              void* d_out, int out_size) {
    (void)in_sizes; (void)n_in; (void)out_size;
    const float* features = (const float*)d_in[0];
    const int*   captions = (const int*)d_in[1];
    const float* enc   = (const float*)d_in[3];
    const float* table = (const float*)d_in[4];
    const float* ft1w  = (const float*)d_in[5];
    const float* ft1b  = (const float*)d_in[6];
    const float* ft2w  = (const float*)d_in[7];
    const float* ft2b  = (const float*)d_in[8];
    const float* wih0  = (const float*)d_in[9];
    const float* whh0  = (const float*)d_in[10];
    const float* bih0  = (const float*)d_in[11];
    const float* bhh0  = (const float*)d_in[12];
    const float* wih1  = (const float*)d_in[13];
    const float* whh1  = (const float*)d_in[14];
    const float* bih1  = (const float*)d_in[15];
    const float* bhh1  = (const float*)d_in[16];
    const float* fcw   = (const float*)d_in[17];
    const float* fcb   = (const float*)d_in[18];
    float* out = (float*)d_out;

    static int smem_set = 0;
    if (!smem_set) {
        cudaFuncSetAttribute(fc_mma_kernel, cudaFuncAttributeMaxDynamicSharedMemorySize, 65536);
        cudaFuncSetAttribute(step_b_kernel, cudaFuncAttributeMaxDynamicSharedMemorySize, 73728);
        cudaFuncSetAttribute(step_d_kernel, cudaFuncAttributeMaxDynamicSharedMemorySize, 73728);
        smem_set = 1;
    }

    launch_pdl(prepW0_kernel, dim3(64, 48), dim3(256), 0, wih0, whh0);
    launch_pdl(prepW1_kernel, dim3(64, 32), dim3(256), 0, wih1, whh1);
    launch_pdl(prepB_kernel, dim3(8), dim3(256), 0, bih0, bhh0, bih1, bhh1);
    launch_pdl(embed_kernel, dim3(4096), dim3(256), 0, captions, table);
    launch_pdl(feat1_kernel, dim3(2048), dim3(256), 0, features, ft1w, ft1b);
    launch_pdl(feat2_kernel, dim3(2048), dim3(256), 0, ft2w, ft2b);
    launch_pdl(splitW_kernel, dim3(16000), dim3(256), 0, fcw);
    launch_pdl(lstm0_pre_kernel, dim3(8, 64), dim3(256), 0);

    for (int t = 0; t < 64; t++) {
        launch_pdl(step_a_kernel, dim3(160), dim3(256), 0, enc);
        launch_pdl(step_b_kernel, dim3(64), dim3(256), (size_t)73728);
        launch_pdl(step_red0_kernel, dim3(64), dim3(256), 0, t);
        launch_pdl(step_d_kernel, dim3(64), dim3(256), (size_t)73728);
        launch_pdl(step_red1_kernel, dim3(64), dim3(256), 0, t);
    }

    launch_pdl(fc_mma_kernel, dim3(250, 16), dim3(256), (size_t)65536, fcb, out);
}

// round 17
// speedup vs baseline: 2.1642x; 1.3423x over previous
#include <cuda_runtime.h>
#include <cuda_bf16.h>
#include <math.h>
#include <stdint.h>

#define FULLMASK 0xffffffffu

// ---------------- persistent device scratch ----------------
__device__ float g_W0T[1536 * 2048];      // layer0 weights [k][j*4+gate] (k: emb|ctx|h0)
__device__ float g_W1T[1024 * 2048];      // layer1 weights [k][j*4+gate] (k: h0|h1)
__device__ float g_b0[2048];
__device__ float g_b1[2048];
__device__ float g_embT[64 * 512 * 32];   // embeddings [t][k][b]
__device__ float g_emb0[64 * 2048 * 32];  // precomputed emb @ W0e, [t][jj][b]
__device__ float g_f1[32 * 512];
__device__ float g_h0T[512 * 32];         // h0 state [j][b]
__device__ float g_h1T[512 * 32];         // h1 state [j][b]
__device__ float g_c0T[512 * 32];
__device__ float g_c1T[512 * 32];
__device__ float g_ctxT[512 * 32];
__device__ float g_part0[128 * 8192];     // [jx*16+ks][(jloc*4+g)*32+b] (ks0-7 ctx, 8-15 h0)
__device__ float g_part1[128 * 8192];     // (ks0-7 h0-half, 8-15 h1-half)
// bf16 split operands for tensor-core FC
__device__ __align__(16) __nv_bfloat16 g_hsH[2048 * 512];
__device__ __align__(16) __nv_bfloat16 g_hsL[2048 * 512];
__device__ __align__(16) __nv_bfloat16 g_fcwH[32000 * 512];
__device__ __align__(16) __nv_bfloat16 g_fcwL[32000 * 512];

extern __shared__ char g_smem_raw[];

// ---------------- helpers ----------------
static __device__ __forceinline__ float sigmoidf_(float x) { return 1.f / (1.f + expf(-x)); }

static __device__ __forceinline__ float warp_sum(float v) {
#pragma unroll
    for (int o = 16; o; o >>= 1) v += __shfl_xor_sync(FULLMASK, v, o);
    return v;
}

static __device__ __forceinline__ unsigned long long pack2(float lo, float hi) {
    unsigned long long r;
    asm("mov.b64 %0, {%1, %2};" : "=l"(r) : "f"(lo), "f"(hi));
    return r;
}
static __device__ __forceinline__ void unpack2(unsigned long long v, float& lo, float& hi) {
    asm("mov.b64 {%0, %1}, %2;" : "=f"(lo), "=f"(hi) : "l"(v));
}
#define FMA2(acc, a, b) asm("fma.rn.f32x2 %0, %1, %2, %0;" : "+l"(acc) : "l"(a), "l"(b))

static __device__ __forceinline__ uint32_t smem_to_u32(const void* p) {
    uint32_t a;
    asm("{ .reg .u64 tmp; cvta.to.shared.u64 tmp, %1; cvt.u32.u64 %0, tmp; }" : "=r"(a) : "l"(p));
    return a;
}

#define GDC_WAIT()    asm volatile("griddepcontrol.wait;" ::: "memory")
#define GDC_TRIGGER() asm volatile("griddepcontrol.launch_dependents;" ::: "memory")

#define LDMATRIX_X4(r0, r1, r2, r3, addr) \
    asm volatile("ldmatrix.sync.aligned.m8n8.x4.shared.b16 {%0,%1,%2,%3}, [%4];" \
                 : "=r"(r0), "=r"(r1), "=r"(r2), "=r"(r3) : "r"(addr))
#define LDMATRIX_X2(r0, r1, addr) \
    asm volatile("ldmatrix.sync.aligned.m8n8.x2.shared.b16 {%0,%1}, [%2];" \
                 : "=r"(r0), "=r"(r1) : "r"(addr))

#define MMA_BF16(c, a, b) \
    asm volatile("mma.sync.aligned.m16n8k16.row.col.f32.bf16.bf16.f32 " \
                 "{%0,%1,%2,%3}, {%4,%5,%6,%7}, {%8,%9}, {%0,%1,%2,%3};" \
                 : "+f"((c)[0]), "+f"((c)[1]), "+f"((c)[2]), "+f"((c)[3]) \
                 : "r"((a)[0]), "r"((a)[1]), "r"((a)[2]), "r"((a)[3]), \
                   "r"((b)[0]), "r"((b)[1]))

// ---------------- GEMM partial: 64-k-chunk, global weights ----------------
static __device__ __forceinline__ void mm_chunk(const float* __restrict__ W0,
                                                const float* xs, int j, int bg,
                                                float* __restrict__ dst_slot) {
    const float4* W = (const float4*)(W0 + j * 4);
    unsigned long long acc[4][4];
#pragma unroll
    for (int g = 0; g < 4; g++)
#pragma unroll
        for (int p = 0; p < 4; p++) acc[g][p] = 0ull;
    const float* xr = xs + bg * 8;
#pragma unroll 8
    for (int k = 0; k < 64; k++) {
        float4 w = W[(size_t)k * 512];
        unsigned long long wx = pack2(w.x, w.x);
        unsigned long long wy = pack2(w.y, w.y);
        unsigned long long wz = pack2(w.z, w.z);
        unsigned long long ww = pack2(w.w, w.w);
        const unsigned long long* xp = (const unsigned long long*)(xr + k * 32);
#pragma unroll
        for (int p = 0; p < 4; p++) {
            unsigned long long xv = xp[p];
            FMA2(acc[0][p], wx, xv);
            FMA2(acc[1][p], wy, xv);
            FMA2(acc[2][p], wz, xv);
            FMA2(acc[3][p], ww, xv);
        }
    }
    float* dst = dst_slot + (j * 4) * 32 + bg * 8;
#pragma unroll
    for (int g = 0; g < 4; g++)
#pragma unroll
        for (int p = 0; p < 4; p++) {
            float lo, hi;
            unpack2(acc[g][p], lo, hi);
            *(float2*)(dst + g * 32 + 2 * p) = make_float2(lo, hi);
        }
}

// gate-quad reduction (coalesced: warp spans b) over the 16 part slots
static __device__ __forceinline__ void reduce_gates(const float* __restrict__ part,
                                                    int j, int b,
                                                    float& s0, float& s1,
                                                    float& s2, float& s3) {
    const float* base = part + (size_t)(j >> 6) * 16 * 8192 + ((j & 63) * 4) * 32 + b;
#pragma unroll
    for (int k2 = 0; k2 < 16; k2++) {
        const float* p = base + (size_t)k2 * 8192;
        s0 += p[0];
        s1 += p[32];
        s2 += p[64];
        s3 += p[96];
    }
}

// ---------------- prep1: all independent preprocessing, fused by CTA range ----------------
// ranges: [0,3072) prepW0 | [3072,5120) prepW1 | [5120,5128) prepB |
//         [5128,9224) embed | [9224,11272) feat1 | [11272,27272) splitW
__global__ __launch_bounds__(256) void prep1_kernel(
    const float* __restrict__ wih0, const float* __restrict__ whh0,
    const float* __restrict__ wih1, const float* __restrict__ whh1,
    const float* __restrict__ bih0, const float* __restrict__ bhh0,
    const float* __restrict__ bih1, const float* __restrict__ bhh1,
    const int* __restrict__ cap, const float* __restrict__ table,
    const float* __restrict__ features, const float* __restrict__ ft1w,
    const float* __restrict__ ft1b, const float* __restrict__ fcw) {
    GDC_WAIT();
    __shared__ float tile[32][33];
    int cta = blockIdx.x, tid = threadIdx.x;

    if (cta < 3072) {
        // prepW0: tiled transpose
        int jj0 = (cta & 63) * 32;
        int k0 = (cta >> 6) * 32;
        int tx = tid & 31, ty = tid >> 5;
        for (int jjl = ty; jjl < 32; jjl += 8) {
            int jj = jj0 + jjl;
            int j = jj >> 2, g = jj & 3;
            int row = g * 512 + j;
            int k = k0 + tx;
            float v = (k < 1024) ? wih0[row * 1024 + k] : whh0[row * 512 + (k - 1024)];
            tile[jjl][tx] = v;
        }
        __syncthreads();
        for (int kl = ty; kl < 32; kl += 8)
            g_W0T[(size_t)(k0 + kl) * 2048 + jj0 + tx] = tile[tx][kl];
    } else if (cta < 5120) {
        // prepW1
        int c = cta - 3072;
        int jj0 = (c & 63) * 32;
        int k0 = (c >> 6) * 32;
        int tx = tid & 31, ty = tid >> 5;
        for (int jjl = ty; jjl < 32; jjl += 8) {
            int jj = jj0 + jjl;
            int j = jj >> 2, g = jj & 3;
            int row = g * 512 + j;
            int k = k0 + tx;
            float v = (k < 512) ? wih1[row * 512 + k] : whh1[row * 512 + (k - 512)];
            tile[jjl][tx] = v;
        }
        __syncthreads();
        for (int kl = ty; kl < 32; kl += 8)
            g_W1T[(size_t)(k0 + kl) * 2048 + jj0 + tx] = tile[tx][kl];
    } else if (cta < 5128) {
        // prepB
        int jj = (cta - 5120) * 256 + tid;
        int j = jj >> 2, g = jj & 3;
        int row = g * 512 + j;
        g_b0[jj] = bih0[row] + bhh0[row];
        g_b1[jj] = bih1[row] + bhh1[row];
    } else if (cta < 9224) {
        // embed
        int idx = (cta - 5128) * 256 + tid;
        int b = idx >> 15;
        int t = (idx >> 9) & 63;
        int k = idx & 511;
        int tok = cap[b * 64 + t];
        g_embT[(t * 512 + k) * 32 + b] = table[(size_t)tok * 512 + k];
    } else if (cta < 11272) {
        // feat1
        int gid = (cta - 9224) * 8 + (tid >> 5);
        int lane = tid & 31;
        int b = gid >> 9, j = gid & 511;
        const float* fr = features + b * 2048;
        const float* wr = ft1w + j * 2048;
        float a = 0.f;
        for (int k = lane; k < 2048; k += 32) a = fmaf(fr[k], wr[k], a);
        a = warp_sum(a);
        if (!lane) g_f1[gid] = fmaxf(a + ft1b[j], 0.f);
    } else {
        // splitW (vectorized)
        int idx = ((cta - 11272) * 256 + tid) * 4;
        float4 v = *(const float4*)(fcw + idx);
        __nv_bfloat16 h0 = __float2bfloat16(v.x), h1 = __float2bfloat16(v.y);
        __nv_bfloat16 h2 = __float2bfloat16(v.z), h3 = __float2bfloat16(v.w);
        __nv_bfloat162 hA, hB, lA, lB;
        hA.x = h0; hA.y = h1; hB.x = h2; hB.y = h3;
        lA.x = __float2bfloat16(v.x - __bfloat162float(h0));
        lA.y = __float2bfloat16(v.y - __bfloat162float(h1));
        lB.x = __float2bfloat16(v.z - __bfloat162float(h2));
        lB.y = __float2bfloat16(v.w - __bfloat162float(h3));
        *(__nv_bfloat162*)(g_fcwH + idx) = hA;
        *(__nv_bfloat162*)(g_fcwH + idx + 2) = hB;
        *(__nv_bfloat162*)(g_fcwL + idx) = lA;
        *(__nv_bfloat162*)(g_fcwL + idx + 2) = lB;
    }
    GDC_TRIGGER();
}

// ---------------- prep2: feat2 (2048 CTAs) || lstm0_pre (512 CTAs) ----------------
__global__ __launch_bounds__(256) void prep2_kernel(const float* __restrict__ ft2w,
                                                    const float* __restrict__ ft2b) {
    GDC_WAIT();
    __shared__ float xs[64 * 32];
    int cta = blockIdx.x, tid = threadIdx.x;

    if (cta < 2048) {
        // feat2: init h/c states
        int gid = cta * 8 + (tid >> 5);
        int lane = tid & 31;
        int b = gid >> 9, j = gid & 511;
        const float* fr = g_f1 + b * 512;
        const float* wr = ft2w + j * 512;
        float a = 0.f;
        for (int k = lane; k < 512; k += 32) a = fmaf(fr[k], wr[k], a);
        a = warp_sum(a);
        if (!lane) {
            float v = a + ft2b[j];
            int jb = j * 32 + b;
            g_h0T[jb] = v;
            g_h1T[jb] = v;
            g_c0T[jb] = v;
            g_c1T[jb] = v;
        }
        GDC_TRIGGER();
        return;
    }

    // lstm0_pre: c = cta-2048, jx = c&7, t = c>>3
    int c = cta - 2048;
    int jx = c & 7, t = c >> 3;
    int j = tid & 63, bg = tid >> 6;
    int jjbase = (jx * 64 + j) * 4;
    const float* embt = g_embT + (size_t)t * 512 * 32;

    unsigned long long acc[4][4];
#pragma unroll
    for (int g = 0; g < 4; g++)
#pragma unroll
        for (int p = 0; p < 4; p++) acc[g][p] = 0ull;

    for (int ck = 0; ck < 8; ck++) {
        __syncthreads();
        for (int i = tid; i < 64 * 32; i += 256) xs[i] = embt[ck * 2048 + i];
        __syncthreads();
        const float4* W = (const float4*)(g_W0T + (size_t)(ck * 64) * 2048 + jjbase);
        const float* xr = xs + bg * 8;
#pragma unroll 4
        for (int k = 0; k < 64; k++) {
            float4 w = W[(size_t)k * 512];
            unsigned long long wx = pack2(w.x, w.x);
            unsigned long long wy = pack2(w.y, w.y);
            unsigned long long wz = pack2(w.z, w.z);
            unsigned long long ww = pack2(w.w, w.w);
            const unsigned long long* xp = (const unsigned long long*)(xr + k * 32);
#pragma unroll
            for (int p = 0; p < 4; p++) {
                unsigned long long xv = xp[p];
                FMA2(acc[0][p], wx, xv);
                FMA2(acc[1][p], wy, xv);
                FMA2(acc[2][p], wz, xv);
                FMA2(acc[3][p], ww, xv);
            }
        }
    }
#pragma unroll
    for (int g = 0; g < 4; g++) {
        float* dst = g_emb0 + ((size_t)t * 2048 + jjbase + g) * 32 + bg * 8;
#pragma unroll
        for (int p = 0; p < 4; p++) {
            float lo, hi;
            unpack2(acc[g][p], lo, hi);
            *(float2*)(dst + 2 * p) = make_float2(lo, hi);
        }
    }
    GDC_TRIGGER();
}

// ---- Node A: attn (32) || mm0 h0-half (64) || mm1 h1-half (64); all deps from t-1 ----
__global__ __launch_bounds__(256) void step_a_kernel(const float* __restrict__ enc) {
    GDC_WAIT();
    __shared__ float sbuf[2048];
    int cta = blockIdx.x, tid = threadIdx.x;

    if (cta < 64) {
        int jx = cta & 7, ks = cta >> 3;
        int j = tid & 63, bg = tid >> 6;
        for (int i = tid; i < 64 * 32; i += 256) sbuf[i] = g_h0T[ks * 2048 + i];
        __syncthreads();
        mm_chunk(g_W0T + (size_t)(1024 + ks * 64) * 2048 + jx * 256, sbuf, j, bg,
                 g_part0 + (size_t)(jx * 16 + 8 + ks) * 8192);
        GDC_TRIGGER();
        return;
    }
    if (cta < 128) {
        int c = cta - 64;
        int jx = c & 7, ks = c >> 3;
        int j = tid & 63, bg = tid >> 6;
        for (int i = tid; i < 64 * 32; i += 256) sbuf[i] = g_h1T[ks * 2048 + i];
        __syncthreads();
        mm_chunk(g_W1T + (size_t)(512 + ks * 64) * 2048 + jx * 256, sbuf, j, bg,
                 g_part1 + (size_t)(jx * 16 + 8 + ks) * 8192);
        GDC_TRIGGER();
        return;
    }

    // attention for b = cta - 128
    int b = cta - 128;
    float* q = sbuf;
    float* sc = sbuf + 512;
    float* redv = sbuf + 720;
    int lane = tid & 31, wid = tid >> 5;

    for (int i = tid; i < 512; i += 256) q[i] = g_h1T[i * 32 + b];
    __syncthreads();

    for (int s = wid; s < 196; s += 8) {
        const float* e = enc + ((size_t)b * 196 + s) * 512;
        float a = 0.f;
#pragma unroll
        for (int k = lane; k < 512; k += 32) a = fmaf(q[k], e[k], a);
        a = warp_sum(a);
        if (!lane) sc[s] = a * 0.04419417382415922f;
    }
    __syncthreads();

    float v = (tid < 196) ? sc[tid] : -1e30f;
    float m = v;
#pragma unroll
    for (int o = 16; o; o >>= 1) m = fmaxf(m, __shfl_xor_sync(FULLMASK, m, o));
    if (!lane) redv[wid] = m;
    __syncthreads();
    m = redv[0];
#pragma unroll
    for (int i = 1; i < 8; i++) m = fmaxf(m, redv[i]);
    float ev = (tid < 196) ? expf(v - m) : 0.f;
    float s = warp_sum(ev);
    if (!lane) redv[8 + wid] = s;
    __syncthreads();
    s = 0.f;
#pragma unroll
    for (int i = 0; i < 8; i++) s += redv[8 + i];
    if (tid < 196) sc[tid] = ev / s;
    __syncthreads();

    {
        const float* e = enc + (size_t)b * 196 * 512 + tid;
        float a0 = 0.f, a1 = 0.f;
#pragma unroll 4
        for (int ss = 0; ss < 196; ss++) {
            float w = sc[ss];
            a0 = fmaf(w, e[(size_t)ss * 512], a0);
            a1 = fmaf(w, e[(size_t)ss * 512 + 256], a1);
        }
        g_ctxT[tid * 32 + b] = a0;
        g_ctxT[(tid + 256) * 32 + b] = a1;
    }
    GDC_TRIGGER();
}

// ---------------- Node B: mm0 ctx-half (64 CTAs) ----------------
__global__ __launch_bounds__(256) void step_b_kernel() {
    GDC_WAIT();
    __shared__ float sbuf[2048];
    int cta = blockIdx.x, tid = threadIdx.x;
    int jx = cta & 7, ks = cta >> 3;
    int j = tid & 63, bg = tid >> 6;
    for (int i = tid; i < 64 * 32; i += 256) sbuf[i] = g_ctxT[ks * 2048 + i];
    __syncthreads();
    mm_chunk(g_W0T + (size_t)(512 + ks * 64) * 2048 + jx * 256, sbuf, j, bg,
             g_part0 + (size_t)(jx * 16 + ks) * 8192);
    GDC_TRIGGER();
}

// ---------------- Node C: wide red0 (64 CTAs, 16K threads) -> h0, c0 ----------------
__global__ __launch_bounds__(256) void step_red0_kernel(int t) {
    GDC_WAIT();
    int idx = blockIdx.x * 256 + threadIdx.x;
    int j = idx >> 5, b = idx & 31;
    const float* emb0t = g_emb0 + (size_t)t * 2048 * 32;
    float4 bs = ((const float4*)g_b0)[j];
    float s0 = bs.x + emb0t[(j * 4 + 0) * 32 + b];
    float s1 = bs.y + emb0t[(j * 4 + 1) * 32 + b];
    float s2 = bs.z + emb0t[(j * 4 + 2) * 32 + b];
    float s3 = bs.w + emb0t[(j * 4 + 3) * 32 + b];
    reduce_gates(g_part0, j, b, s0, s1, s2, s3);
    float gi = sigmoidf_(s0), gf = sigmoidf_(s1);
    float gg = tanhf(s2), go = sigmoidf_(s3);
    int jb = j * 32 + b;
    float c2 = gf * g_c0T[jb] + gi * gg;
    g_c0T[jb] = c2;
    g_h0T[jb] = go * tanhf(c2);
    GDC_TRIGGER();
}

// ---------------- Node D: mm1 h0-half (64 CTAs) ----------------
__global__ __launch_bounds__(256) void step_d_kernel() {
    GDC_WAIT();
    __shared__ float sbuf[2048];
    int cta = blockIdx.x, tid = threadIdx.x;
    int jx = cta & 7, ks = cta >> 3;
    int j = tid & 63, bg = tid >> 6;
    for (int i = tid; i < 64 * 32; i += 256) sbuf[i] = g_h0T[ks * 2048 + i];
    __syncthreads();
    mm_chunk(g_W1T + (size_t)(ks * 64) * 2048 + jx * 256, sbuf, j, bg,
             g_part1 + (size_t)(jx * 16 + ks) * 8192);
    GDC_TRIGGER();
}

// ---------------- Node E: wide red1 (64 CTAs) -> h1, c1, hs splits ----------------
__global__ __launch_bounds__(256) void step_red1_kernel(int t) {
    GDC_WAIT();
    int idx = blockIdx.x * 256 + threadIdx.x;
    int j = idx >> 5, b = idx & 31;
    float4 bs = ((const float4*)g_b1)[j];
    float s0 = bs.x, s1 = bs.y, s2 = bs.z, s3 = bs.w;
    reduce_gates(g_part1, j, b, s0, s1, s2, s3);
    float gi = sigmoidf_(s0), gf = sigmoidf_(s1);
    float gg = tanhf(s2), go = sigmoidf_(s3);
    int jb = j * 32 + b;
    float c2 = gf * g_c1T[jb] + gi * gg;
    g_c1T[jb] = c2;
    float h = go * tanhf(c2);
    g_h1T[jb] = h;
    __nv_bfloat16 hh = __float2bfloat16(h);
    size_t m = (size_t)(t * 32 + b) * 512 + j;
    g_hsH[m] = hh;
    g_hsL[m] = __float2bfloat16(h - __bfloat162float(hh));
    GDC_TRIGGER();
}

// ---------------- tensor-core FC via mma.sync bf16 split ----------------
__global__ __launch_bounds__(256, 1) void fc_mma_kernel(const float* __restrict__ fcb,
                                                        float* __restrict__ out) {
    GDC_WAIT();
    char* smem = g_smem_raw;
    uint32_t sbase = smem_to_u32(smem);
    int tid = threadIdx.x, lane = tid & 31, wid = tid >> 5;
    int mb = blockIdx.y * 128, nb = blockIdx.x * 128;
    int warp_m = (wid & 1) * 64, warp_n = (wid >> 1) * 32;

    float acc[4][4][4];
#pragma unroll
    for (int mi = 0; mi < 4; mi++)
#pragma unroll
        for (int nj = 0; nj < 4; nj++)
#pragma unroll
            for (int r = 0; r < 4; r++) acc[mi][nj][r] = 0.f;

    for (int kc = 0; kc < 8; kc++) {
        __syncthreads();
#pragma unroll
        for (int it = 0; it < 16; it++) {
            int s = tid + it * 256;
            int tile = s >> 10, r = (s >> 3) & 127, c = s & 7;
            const __nv_bfloat16* g;
            if (tile == 0)      g = g_hsH + (size_t)(mb + r) * 512;
            else if (tile == 1) g = g_hsL + (size_t)(mb + r) * 512;
            else if (tile == 2) g = g_fcwH + (size_t)(nb + r) * 512;
            else                g = g_fcwL + (size_t)(nb + r) * 512;
            uint4 v = *(const uint4*)(g + kc * 64 + c * 8);
            uint32_t off = (uint32_t)(r * 128 + c * 16);
            off ^= (off >> 3) & 0x70;
            *(uint4*)(smem + tile * 16384 + off) = v;
        }
        __syncthreads();

#pragma unroll
        for (int ka = 0; ka < 4; ka++) {
            uint32_t a_hi[4][4], a_lo[4][4], b_hi[4][2], b_lo[4][2];
            int rA = warp_m + (lane & 15);
            int sA = ka * 2 + (lane >> 4);
#pragma unroll
            for (int mi = 0; mi < 4; mi++) {
                uint32_t off = (uint32_t)((rA + mi * 16) * 128 + sA * 16);
                off ^= (off >> 3) & 0x70;
                LDMATRIX_X4(a_hi[mi][0], a_hi[mi][1], a_hi[mi][2], a_hi[mi][3], sbase + off);
                LDMATRIX_X4(a_lo[mi][0], a_lo[mi][1], a_lo[mi][2], a_lo[mi][3],
                            sbase + 16384 + off);
            }
            int rB = warp_n + (lane & 7);
            int sB = ka * 2 + ((lane >> 3) & 1);
#pragma unroll
            for (int nj = 0; nj < 4; nj++) {
                uint32_t off = (uint32_t)((rB + nj * 8) * 128 + sB * 16);
                off ^= (off >> 3) & 0x70;
                LDMATRIX_X2(b_hi[nj][0], b_hi[nj][1], sbase + 32768 + off);
                LDMATRIX_X2(b_lo[nj][0], b_lo[nj][1], sbase + 49152 + off);
            }
#pragma unroll
            for (int mi = 0; mi < 4; mi++)
#pragma unroll
                for (int nj = 0; nj < 4; nj++) {
                    MMA_BF16(acc[mi][nj], a_hi[mi], b_hi[nj]);
                    MMA_BF16(acc[mi][nj], a_hi[mi], b_lo[nj]);
                    MMA_BF16(acc[mi][nj], a_lo[mi], b_hi[nj]);
                }
        }
    }

    int g = lane >> 2, q = lane & 3;
#pragma unroll
    for (int mi = 0; mi < 4; mi++) {
#pragma unroll
        for (int nj = 0; nj < 4; nj++) {
            int m = mb + warp_m + mi * 16 + g;
            int n = nb + warp_n + nj * 8 + q * 2;
            float2 bb = *(const float2*)(fcb + n);
            *(float2*)(out + (size_t)m * 32000 + n) =
                make_float2(acc[mi][nj][0] + bb.x, acc[mi][nj][1] + bb.y);
            *(float2*)(out + (size_t)(m + 8) * 32000 + n) =
                make_float2(acc[mi][nj][2] + bb.x, acc[mi][nj][3] + bb.y);
        }
    }
}

// ---------------- PDL launch helper ----------------
template <typename K, typename... Args>
static void launch_pdl(K kernel, dim3 grid, dim3 block, size_t smem, Args... args) {
    cudaLaunchConfig_t cfg = {};
    cfg.gridDim = grid;
    cfg.blockDim = block;
    cfg.dynamicSmemBytes = smem;
    cfg.stream = 0;
    cudaLaunchAttribute at[1];
    at[0].id = cudaLaunchAttributeProgrammaticStreamSerialization;
    at[0].val.programmaticStreamSerializationAllowed = 1;
    cfg.attrs = at;
    cfg.numAttrs = 1;
    cudaLaunchKernelEx(&cfg, kernel, args...);
}

// ---------------- launch ----------------
extern "C" void kernel_launch(void* const* d_in, const int* in_sizes, int n_in,
                              void* d_out, int out_size) {
    (void)in_sizes; (void)n_in; (void)out_size;
    const float* features = (const float*)d_in[0];
    const int*   captions = (const int*)d_in[1];
    const float* enc   = (const float*)d_in[3];
    const float* table = (const float*)d_in[4];
    const float* ft1w  = (const float*)d_in[5];
    const float* ft1b  = (const float*)d_in[6];
    const float* ft2w  = (const float*)d_in[7];
    const float* ft2b  = (const float*)d_in[8];
    const float* wih0  = (const float*)d_in[9];
    const float* whh0  = (const float*)d_in[10];
    const float* bih0  = (const float*)d_in[11];
    const float* bhh0  = (const float*)d_in[12];
    const float* wih1  = (const float*)d_in[13];
    const float* whh1  = (const float*)d_in[14];
    const float* bih1  = (const float*)d_in[15];
    const float* bhh1  = (const float*)d_in[16];
    const float* fcw   = (const float*)d_in[17];
    const float* fcb   = (const float*)d_in[18];
    float* out = (float*)d_out;

    static int smem_set = 0;
    if (!smem_set) {
        cudaFuncSetAttribute(fc_mma_kernel, cudaFuncAttributeMaxDynamicSharedMemorySize, 65536);
        smem_set = 1;
    }

    launch_pdl(prep1_kernel, dim3(27272), dim3(256), 0,
               wih0, whh0, wih1, whh1, bih0, bhh0, bih1, bhh1,
               captions, table, features, ft1w, ft1b, fcw);
    launch_pdl(prep2_kernel, dim3(2560), dim3(256), 0, ft2w, ft2b);

    for (int t = 0; t < 64; t++) {
        launch_pdl(step_a_kernel, dim3(160), dim3(256), 0, enc);
        launch_pdl(step_b_kernel, dim3(64), dim3(256), 0);
        launch_pdl(step_red0_kernel, dim3(64), dim3(256), 0, t);
        launch_pdl(step_d_kernel, dim3(64), dim3(256), 0);
        launch_pdl(step_red1_kernel, dim3(64), dim3(256), 0, t);
    }

    launch_pdl(fc_mma_kernel, dim3(250, 16), dim3(256), (size_t)65536, fcb, out);
}